// round 16
// baseline (speedup 1.0000x reference)
#include <cuda_runtime.h>
#include <cstdint>
#include <climits>

// Geometry fixed by setup_inputs: (16, 4, 1024, 1024) float32
#define BATCH 16
#define HH 1024
#define WW 1024
#define HW (HH * WW)

#define SROWS 16                   // output rows per warp strip
#define WARPS 4
#define THREADS (WARPS * 32)       // 128
#define ROWS_PER_BLOCK (WARPS * SROWS)  // 64

#define RED_X 128
#define NPART (RED_X * BATCH)      // 2048 partials

__device__ float g_partials[NPART];

// ---------------------------------------------------------------------------
// Stage 1: per-block max(|u|,|v|) partials (unconditional writes, no reset).
// ---------------------------------------------------------------------------
__global__ __launch_bounds__(256)
void maxabs_kernel(const float* __restrict__ in) {
    const float4* __restrict__ base =
        reinterpret_cast<const float4*>(in + (size_t)blockIdx.y * 4 * HW);
    const int n4 = 2 * HW / 4;
    float m = 0.0f;
    #pragma unroll 8
    for (int i = blockIdx.x * 256 + threadIdx.x; i < n4; i += RED_X * 256) {
        float4 vv = base[i];
        m = fmaxf(m, fabsf(vv.x));
        m = fmaxf(m, fabsf(vv.y));
        m = fmaxf(m, fabsf(vv.z));
        m = fmaxf(m, fabsf(vv.w));
    }
    #pragma unroll
    for (int o = 16; o > 0; o >>= 1)
        m = fmaxf(m, __shfl_xor_sync(0xFFFFFFFFu, m, o));
    __shared__ float smax[8];
    int lane = threadIdx.x & 31, wid = threadIdx.x >> 5;
    if (lane == 0) smax[wid] = m;
    __syncthreads();
    if (threadIdx.x == 0) {
        float mm = smax[0];
        #pragma unroll
        for (int w = 1; w < 8; w++) mm = fmaxf(mm, smax[w]);
        g_partials[blockIdx.y * RED_X + blockIdx.x] = mm;
    }
}

__device__ __forceinline__ float upwind1(float c, float l, float r,
                                         float t, float d, float u, float v,
                                         float inv_dx, float dt) {
    float dTdx = (u > 0.0f) ? (c - l) * inv_dx
                            : ((u < 0.0f) ? (r - c) * inv_dx : 0.0f);
    float dTdy = (v > 0.0f) ? (c - t) * inv_dx
                            : ((v < 0.0f) ? (d - c) * inv_dx : 0.0f);
    return c + dt * (-u * dTdx - v * dTdy);
}

// ---------------------------------------------------------------------------
// Stage 2 (fused, one pass): register-rolling streaming stencil per warp.
// Interior strips (62/64) take a branch-free loop; boundary strips take the
// generic clamped path. __launch_bounds__(128,10) -> <=51 regs, ~62% occ.
// ---------------------------------------------------------------------------
__global__ __launch_bounds__(THREADS, 10)
void fused_kernel(const float* __restrict__ in, float* __restrict__ out,
                  int out_size) {
    __shared__ float swarp[WARPS];
    __shared__ float s_dt;

    const int tid = threadIdx.x;
    const int lane = tid & 31;
    const int wid = tid >> 5;

    // ---- Prologue: reduce 2048 partials -> dt ----
    {
        float m = 0.0f;
        #pragma unroll
        for (int i = 0; i < NPART / THREADS; i++)
            m = fmaxf(m, g_partials[tid + i * THREADS]);
        #pragma unroll
        for (int o = 16; o > 0; o >>= 1)
            m = fmaxf(m, __shfl_xor_sync(0xFFFFFFFFu, m, o));
        if (lane == 0) swarp[wid] = m;
        __syncthreads();
        if (tid == 0) {
            float mm = swarp[0];
            #pragma unroll
            for (int w = 1; w < WARPS; w++) mm = fmaxf(mm, swarp[w]);
            const float dx = (float)(1.0 / 126.0);
            float dt_advect = 0.5f * 0.1f * dx / mm;
            float dx2 = dx * dx;
            float dt_diffuse = 0.5f * (dx2 * dx2) / (dx2 + dx2);
            s_dt = fminf(dt_advect, dt_diffuse);
        }
        __syncthreads();
    }
    const float dt = s_dt;

    const float dx = (float)(1.0 / 126.0);
    const float inv_dx = 1.0f / dx;
    const float dx2 = dx * dx;
    const float lap_scale = 0.25f / dx2;

    const int x0 = blockIdx.x * 128;
    const int wy0 = (blockIdx.y * WARPS + wid) * SROWS;
    const int b = blockIdx.z;
    const bool clampL = (x0 == 0);
    const bool clampR = (x0 + 128 == WW);

    const float* __restrict__ U  = in + (size_t)b * 4 * HW;
    const float* __restrict__ V  = U + HW;
    const float* __restrict__ T  = U + 2 * HW;
    const float* __restrict__ Ra = U + 3 * HW;
    float* __restrict__ outb = out + (size_t)b * HW;

    const int gxq = x0 + (lane << 2);   // this thread's quad base column

    float4 Tm, Tc, Tp;
    float4 c4, hq, h1, h2, cprev;

    const bool interior = (wy0 >= 2) && (wy0 + SROWS + 1 <= HH - 1);

    if (interior) {
        // ---- Branch-free interior path ----
        Tm = *reinterpret_cast<const float4*>(T + (size_t)(wy0 - 2) * WW + gxq);
        Tc = *reinterpret_cast<const float4*>(T + (size_t)(wy0 - 1) * WW + gxq);
        const bool eact = ((lane == 0) && !clampL) || ((lane == 31) && !clampR);

        #pragma unroll 2
        for (int k = 0; k <= SROWS + 1; k++) {
            const size_t ro = (size_t)(wy0 - 1 + k) * WW + gxq;
            Tp = *reinterpret_cast<const float4*>(T + ro + WW);
            const float4 u4 = *reinterpret_cast<const float4*>(U + ro);
            const float4 v4 = *reinterpret_cast<const float4*>(V + ro);

            // Horizontal T neighbors via shuffle; warp-edge lanes from global.
            float cl = __shfl_up_sync(0xFFFFFFFFu, Tc.w, 1);
            float cr = __shfl_down_sync(0xFFFFFFFFu, Tc.x, 1);
            if (lane == 0)  cl = clampL ? Tc.x : T[ro - 1];
            if (lane == 31) cr = clampR ? Tc.w : T[ro + 4];

            c4.x = upwind1(Tc.x, cl,   Tc.y, Tm.x, Tp.x, u4.x, v4.x, inv_dx, dt);
            c4.y = upwind1(Tc.y, Tc.x, Tc.z, Tm.y, Tp.y, u4.y, v4.y, inv_dx, dt);
            c4.z = upwind1(Tc.z, Tc.y, Tc.w, Tm.z, Tp.z, u4.z, v4.z, inv_dx, dt);
            c4.w = upwind1(Tc.w, Tc.z, cr,   Tm.w, Tp.w, u4.w, v4.w, inv_dx, dt);

            // Strip-edge T1 (merged lane0/lane31 predicated block).
            float t1e = 0.0f;
            if (eact) {
                const size_t exo  = (lane == 0) ? (ro - 1) : (ro + 4);
                const float c     = T[exo];
                const float outer = (lane == 0) ? T[exo - 1] : T[exo + 1];
                const float inner = (lane == 0) ? Tc.x : Tc.w;
                const float t     = T[exo - WW];
                const float d     = T[exo + WW];
                const float uu    = U[exo];
                const float vv    = V[exo];
                const float l  = (lane == 0) ? outer : inner;
                const float rr = (lane == 0) ? inner : outer;
                t1e = upwind1(c, l, rr, t, d, uu, vv, inv_dx, dt);
            }

            float le = __shfl_up_sync(0xFFFFFFFFu, c4.w, 1);
            float re = __shfl_down_sync(0xFFFFFFFFu, c4.x, 1);
            if (lane == 0)  le = clampL ? c4.x : t1e;
            if (lane == 31) re = clampR ? c4.w : t1e;

            hq.x = le   + 2.0f * c4.x + c4.y;
            hq.y = c4.x + 2.0f * c4.y + c4.z;
            hq.z = c4.y + 2.0f * c4.z + c4.w;
            hq.w = c4.z + 2.0f * c4.w + re;

            if (k >= 2) {
                const size_t go = ro - WW;     // output row r-1
                const float4 ra = *reinterpret_cast<const float4*>(Ra + go);
                float4 res;
                res.x = cprev.x + dt * (lap_scale * (h2.x + 2.0f * h1.x + hq.x - 16.0f * cprev.x) + ra.x);
                res.y = cprev.y + dt * (lap_scale * (h2.y + 2.0f * h1.y + hq.y - 16.0f * cprev.y) + ra.y);
                res.z = cprev.z + dt * (lap_scale * (h2.z + 2.0f * h1.z + hq.z - 16.0f * cprev.z) + ra.z);
                res.w = cprev.w + dt * (lap_scale * (h2.w + 2.0f * h1.w + hq.w - 16.0f * cprev.w) + ra.w);
                *reinterpret_cast<float4*>(outb + go) = res;
            }

            h2 = h1; h1 = hq; cprev = c4;
            Tm = Tc; Tc = Tp;
        }
    } else {
        // ---- Generic clamped path (first/last strip only) ----
        int rt_prev = INT_MIN;
        for (int k = 0; k <= SROWS + 1; k++) {
            int r = wy0 - 1 + k;
            int rt = min(max(r, 0), HH - 1);

            if (rt != rt_prev) {
                int rtm = max(rt - 1, 0);
                int rtp = min(rt + 1, HH - 1);
                if (k == 0) {
                    Tm = *reinterpret_cast<const float4*>(T + (size_t)rtm * WW + gxq);
                    Tc = *reinterpret_cast<const float4*>(T + (size_t)rt  * WW + gxq);
                } else {
                    Tm = Tc; Tc = Tp;
                }
                Tp = *reinterpret_cast<const float4*>(T + (size_t)rtp * WW + gxq);
                float4 u4 = *reinterpret_cast<const float4*>(U + (size_t)rt * WW + gxq);
                float4 v4 = *reinterpret_cast<const float4*>(V + (size_t)rt * WW + gxq);

                float cl = __shfl_up_sync(0xFFFFFFFFu, Tc.w, 1);
                float cr = __shfl_down_sync(0xFFFFFFFFu, Tc.x, 1);
                if (lane == 0)  cl = clampL ? Tc.x : T[(size_t)rt * WW + (x0 - 1)];
                if (lane == 31) cr = clampR ? Tc.w : T[(size_t)rt * WW + (x0 + 128)];

                c4.x = upwind1(Tc.x, cl,   Tc.y, Tm.x, Tp.x, u4.x, v4.x, inv_dx, dt);
                c4.y = upwind1(Tc.y, Tc.x, Tc.z, Tm.y, Tp.y, u4.y, v4.y, inv_dx, dt);
                c4.z = upwind1(Tc.z, Tc.y, Tc.w, Tm.z, Tp.z, u4.z, v4.z, inv_dx, dt);
                c4.w = upwind1(Tc.w, Tc.z, cr,   Tm.w, Tp.w, u4.w, v4.w, inv_dx, dt);

                float t1e = 0.0f;
                if (lane == 0 && !clampL) {
                    int ex = x0 - 1;
                    size_t rowo = (size_t)rt * WW;
                    float c = T[rowo + ex];
                    float l = T[rowo + max(ex - 1, 0)];
                    float t = T[(size_t)rtm * WW + ex];
                    float d = T[(size_t)rtp * WW + ex];
                    float uu = U[rowo + ex];
                    float vv = V[rowo + ex];
                    t1e = upwind1(c, l, Tc.x, t, d, uu, vv, inv_dx, dt);
                }
                if (lane == 31 && !clampR) {
                    int ex = x0 + 128;
                    size_t rowo = (size_t)rt * WW;
                    float c = T[rowo + ex];
                    float rr = T[rowo + min(ex + 1, WW - 1)];
                    float t = T[(size_t)rtm * WW + ex];
                    float d = T[(size_t)rtp * WW + ex];
                    float uu = U[rowo + ex];
                    float vv = V[rowo + ex];
                    t1e = upwind1(c, Tc.w, rr, t, d, uu, vv, inv_dx, dt);
                }

                float le = __shfl_up_sync(0xFFFFFFFFu, c4.w, 1);
                float re = __shfl_down_sync(0xFFFFFFFFu, c4.x, 1);
                if (lane == 0)  le = clampL ? c4.x : t1e;
                if (lane == 31) re = clampR ? c4.w : t1e;

                hq.x = le   + 2.0f * c4.x + c4.y;
                hq.y = c4.x + 2.0f * c4.y + c4.z;
                hq.z = c4.y + 2.0f * c4.z + c4.w;
                hq.w = c4.z + 2.0f * c4.w + re;

                rt_prev = rt;
            }

            if (k >= 2) {
                int oy = wy0 + k - 2;
                size_t gidx = (size_t)oy * WW + gxq;
                float4 ra = *reinterpret_cast<const float4*>(Ra + gidx);
                float4 res;
                res.x = cprev.x + dt * (lap_scale * (h2.x + 2.0f * h1.x + hq.x - 16.0f * cprev.x) + ra.x);
                res.y = cprev.y + dt * (lap_scale * (h2.y + 2.0f * h1.y + hq.y - 16.0f * cprev.y) + ra.y);
                res.z = cprev.z + dt * (lap_scale * (h2.z + 2.0f * h1.z + hq.z - 16.0f * cprev.z) + ra.z);
                res.w = cprev.w + dt * (lap_scale * (h2.w + 2.0f * h1.w + hq.w - 16.0f * cprev.w) + ra.w);
                *reinterpret_cast<float4*>(outb + gidx) = res;
            }

            h2 = h1; h1 = hq; cprev = c4;
        }
    }

    if (tid == 0 && blockIdx.x == 0 && blockIdx.y == 0 && blockIdx.z == 0) {
        out[out_size - 1] = dt;
    }
}

extern "C" void kernel_launch(void* const* d_in, const int* in_sizes, int n_in,
                              void* d_out, int out_size) {
    const float* in = (const float*)d_in[0];
    float* out = (float*)d_out;

    dim3 rgrid(RED_X, BATCH);
    maxabs_kernel<<<rgrid, 256>>>(in);

    dim3 fgrid(WW / 128, HH / ROWS_PER_BLOCK, BATCH);  // 8 x 16 x 16 = 2048
    fused_kernel<<<fgrid, THREADS>>>(in, out, out_size);
}

// round 17
// speedup vs baseline: 1.2650x; 1.2650x over previous
#include <cuda_runtime.h>
#include <cstdint>

// Geometry fixed by setup_inputs: (16, 4, 1024, 1024) float32
#define BATCH 16
#define HH 1024
#define WW 1024
#define HW (HH * WW)

#define TILE_W 128
#define TILE_H 64
#define THREADS 512

// Phase-1 T1 region: rows gy = y0-1 .. y0+64 (66), cols gx = x0-4 .. x0+131
// (34 quads of 4). Pitch 136 floats, float4-aligned.
#define P1ROWS (TILE_H + 2)        // 66
#define QPR 34                     // quads per row
#define SPITCH (QPR * 4)           // 136
#define NQUADS (P1ROWS * QPR)      // 2244

#define RED_X 128
#define NPART (RED_X * BATCH)      // 2048 partials
#define RBLOCKS (RED_X * BATCH)    // maxabs block count

__device__ float g_partials[NPART];
__device__ unsigned int g_count;   // zero-init; self-resetting each run
__device__ float g_dt;

// ---------------------------------------------------------------------------
// Stage 1: per-block max(|u|,|v|) partials; the LAST block to finish also
// reduces all partials -> g_dt (threadfence + atomic ticket), then resets
// the ticket counter so every graph replay starts from zero.
// ---------------------------------------------------------------------------
__global__ __launch_bounds__(256)
void maxabs_kernel(const float* __restrict__ in) {
    const float4* __restrict__ base =
        reinterpret_cast<const float4*>(in + (size_t)blockIdx.y * 4 * HW);
    const int n4 = 2 * HW / 4;
    float m = 0.0f;
    #pragma unroll 8
    for (int i = blockIdx.x * 256 + threadIdx.x; i < n4; i += RED_X * 256) {
        float4 vv = base[i];
        m = fmaxf(m, fabsf(vv.x));
        m = fmaxf(m, fabsf(vv.y));
        m = fmaxf(m, fabsf(vv.z));
        m = fmaxf(m, fabsf(vv.w));
    }
    #pragma unroll
    for (int o = 16; o > 0; o >>= 1)
        m = fmaxf(m, __shfl_xor_sync(0xFFFFFFFFu, m, o));
    __shared__ float smax[8];
    __shared__ bool s_last;
    int lane = threadIdx.x & 31, wid = threadIdx.x >> 5;
    if (lane == 0) smax[wid] = m;
    __syncthreads();
    if (threadIdx.x == 0) {
        float mm = smax[0];
        #pragma unroll
        for (int w = 1; w < 8; w++) mm = fmaxf(mm, smax[w]);
        g_partials[blockIdx.y * RED_X + blockIdx.x] = mm;
        __threadfence();
        unsigned int t = atomicAdd(&g_count, 1u);
        s_last = (t == RBLOCKS - 1);
    }
    __syncthreads();

    if (s_last) {
        // Final reduction by the whole last block.
        float mm = 0.0f;
        #pragma unroll
        for (int i = 0; i < NPART / 256; i++)
            mm = fmaxf(mm, g_partials[threadIdx.x + i * 256]);
        #pragma unroll
        for (int o = 16; o > 0; o >>= 1)
            mm = fmaxf(mm, __shfl_xor_sync(0xFFFFFFFFu, mm, o));
        if (lane == 0) smax[wid] = mm;
        __syncthreads();
        if (threadIdx.x == 0) {
            float r = smax[0];
            #pragma unroll
            for (int w = 1; w < 8; w++) r = fmaxf(r, smax[w]);
            const float dx = (float)(1.0 / 126.0);
            float dt_advect = 0.5f * 0.1f * dx / r;
            float dx2 = dx * dx;
            float dt_diffuse = 0.5f * (dx2 * dx2) / (dx2 + dx2);
            g_dt = fminf(dt_advect, dt_diffuse);
            g_count = 0u;   // reset ticket for the next replay
        }
    }
}

// ---------------------------------------------------------------------------
// Stage 2 (fused): read dt (one broadcast float) -> vectorized upwind
// advection into smem -> row-factored 9-pt Laplacian (shuffle edges)
// + RaQ -> float4 out.  (R13 structure, prologue removed.)
// ---------------------------------------------------------------------------
__global__ __launch_bounds__(THREADS, 3)
void fused_kernel(const float* __restrict__ in, float* __restrict__ out,
                  int out_size) {
    __shared__ float sT1[P1ROWS * SPITCH];

    const int tid = threadIdx.x;
    const int x0 = blockIdx.x * TILE_W;
    const int y0 = blockIdx.y * TILE_H;
    const int b  = blockIdx.z;

    const float dt = g_dt;   // written by maxabs_kernel (prior launch)

    const float dx = (float)(1.0 / 126.0);
    const float inv_dx = 1.0f / dx;

    const float* __restrict__ U  = in + (size_t)b * 4 * HW;
    const float* __restrict__ V  = U + HW;
    const float* __restrict__ T  = U + 2 * HW;
    const float* __restrict__ Ra = U + 3 * HW;

    // ---- Phase 1: advection, one float4 quad per iteration ----
    for (int q = tid; q < NQUADS; q += THREADS) {
        int ly = q / QPR;                   // 0..65
        int qi = q - ly * QPR;              // 0..33
        int gx0 = x0 - 4 + (qi << 2);       // quad's first gx (4-aligned)
        int gy = min(max(y0 - 1 + ly, 0), HH - 1);
        int ym = max(gy - 1, 0), yp = min(gy + 1, HH - 1);
        int row = gy * WW;

        float4 res;
        if (gx0 >= 1 && gx0 + 4 <= WW - 1) {
            const float4 c4 = *reinterpret_cast<const float4*>(T + row + gx0);
            const float4 t4 = *reinterpret_cast<const float4*>(T + ym * WW + gx0);
            const float4 d4 = *reinterpret_cast<const float4*>(T + yp * WW + gx0);
            const float4 u4 = *reinterpret_cast<const float4*>(U + row + gx0);
            const float4 v4 = *reinterpret_cast<const float4*>(V + row + gx0);
            float cl = T[row + gx0 - 1];
            float cr = T[row + gx0 + 4];

            float L[6] = {cl, c4.x, c4.y, c4.z, c4.w, cr};
            #pragma unroll
            for (int j = 0; j < 4; j++) {
                float c = L[j + 1];
                float u = (&u4.x)[j];
                float v = (&v4.x)[j];
                float t = (&t4.x)[j];
                float d = (&d4.x)[j];
                float dTdx = (u > 0.0f) ? (c - L[j]) * inv_dx
                                        : ((u < 0.0f) ? (L[j + 2] - c) * inv_dx : 0.0f);
                float dTdy = (v > 0.0f) ? (c - t) * inv_dx
                                        : ((v < 0.0f) ? (d - c) * inv_dx : 0.0f);
                (&res.x)[j] = c + dt * (-u * dTdx - v * dTdy);
            }
        } else {
            #pragma unroll
            for (int j = 0; j < 4; j++) {
                int gx = min(max(gx0 + j, 0), WW - 1);
                int xm = max(gx - 1, 0), xp = min(gx + 1, WW - 1);
                float c = T[row + gx];
                float l = T[row + xm];
                float r = T[row + xp];
                float t = T[ym * WW + gx];
                float d = T[yp * WW + gx];
                float u = U[row + gx];
                float v = V[row + gx];
                float dTdx = (u > 0.0f) ? (c - l) * inv_dx
                                        : ((u < 0.0f) ? (r - c) * inv_dx : 0.0f);
                float dTdy = (v > 0.0f) ? (c - t) * inv_dx
                                        : ((v < 0.0f) ? (d - c) * inv_dx : 0.0f);
                (&res.x)[j] = c + dt * (-u * dTdx - v * dTdy);
            }
        }
        *reinterpret_cast<float4*>(&sT1[ly * SPITCH + (qi << 2)]) = res;
    }
    __syncthreads();

    // ---- Phase 2: row-factored 9-pt Laplacian, vertical 4-row strips;
    //      edge floats via warp shuffle (1 LDS.128/row). ----
    {
        const float dx2 = dx * dx;
        const float lap_scale = 0.25f / dx2;
        const int lane = tid & 31;        // quad column
        const int cy = tid >> 5;          // 0..15
        const int qx = lane << 2;         // 0..124
        const int qy0 = cy << 2;          // 0..60

        float4 ra[4];
        #pragma unroll
        for (int r = 0; r < 4; r++)
            ra[r] = *reinterpret_cast<const float4*>(
                Ra + (size_t)(y0 + qy0 + r) * WW + (x0 + qx));

        float* outb = out + (size_t)b * HW;

        float h_m2[4], h_m1[4], c_m1[4];
        #pragma unroll
        for (int i = 0; i < 6; i++) {
            const float* srow = &sT1[(qy0 + i) * SPITCH];
            float4 m = *reinterpret_cast<const float4*>(srow + qx + 4);
            float le = __shfl_up_sync(0xFFFFFFFFu, m.w, 1);
            float re = __shfl_down_sync(0xFFFFFFFFu, m.x, 1);
            if (lane == 0)  le = srow[3];        // left halo quad's .w
            if (lane == 31) re = srow[132];      // right halo quad's .x

            float h[4];
            h[0] = le  + 2.0f * m.x + m.y;
            h[1] = m.x + 2.0f * m.y + m.z;
            h[2] = m.y + 2.0f * m.z + m.w;
            h[3] = m.z + 2.0f * m.w + re;

            if (i >= 2) {
                int oy = qy0 + i - 2;
                float4 res;
                #pragma unroll
                for (int jj = 0; jj < 4; jj++) {
                    float lap = h_m2[jj] + 2.0f * h_m1[jj] + h[jj]
                              - 16.0f * c_m1[jj];
                    (&res.x)[jj] = c_m1[jj]
                        + dt * (lap_scale * lap + (&ra[i - 2].x)[jj]);
                }
                *reinterpret_cast<float4*>(
                    outb + (size_t)(y0 + oy) * WW + (x0 + qx)) = res;
            }
            #pragma unroll
            for (int jj = 0; jj < 4; jj++) {
                h_m2[jj] = h_m1[jj];
                h_m1[jj] = h[jj];
            }
            c_m1[0] = m.x; c_m1[1] = m.y; c_m1[2] = m.z; c_m1[3] = m.w;
        }
    }

    if (tid == 0 && blockIdx.x == 0 && blockIdx.y == 0 && blockIdx.z == 0) {
        out[out_size - 1] = dt;
    }
}

extern "C" void kernel_launch(void* const* d_in, const int* in_sizes, int n_in,
                              void* d_out, int out_size) {
    const float* in = (const float*)d_in[0];
    float* out = (float*)d_out;

    dim3 rgrid(RED_X, BATCH);
    maxabs_kernel<<<rgrid, 256>>>(in);

    dim3 fgrid(WW / TILE_W, HH / TILE_H, BATCH);  // 8 x 16 x 16 = 2048
    fused_kernel<<<fgrid, THREADS>>>(in, out, out_size);
}